// round 17
// baseline (speedup 1.0000x reference)
#include <cuda_runtime.h>
#include <cuda_bf16.h>

// out[t, e] = cos(t) * s[e] + b[e],  s[e] = sum_q W[e,q]
// E = 1024, T = out_size / E.
//
// R13: evict_last policy retained nothing (256MB stream vs 126MB L2) — dropped.
// All prior designs shared a block-wide 2x__syncthreads + single-commit-thread
// handshake; ~920 cyc/row was invariant. This round removes block coupling
// entirely: WARP-AUTONOMOUS pipelines. Each warp owns whole 4KB rows
// (each thread: 32 columns of constants), fills a private ring slot,
// lane 0 issues fence+bulk+commit, 3-deep ring with wait_group.read 2.
// Only __syncwarp; 16 independent pipelines/SM (2 CTAs x 8 warps, 96KB smem).

#define NBUF 3         // ring depth per warp (3 x 4KB = 12KB/warp, 96KB/CTA)
#define EROW 1024      // embed dim (compile-time; checked at launch)

__global__ __launch_bounds__(256)
void pequant_warp_kernel(const float* __restrict__ W,
                         const float* __restrict__ b,
                         float* __restrict__ out,
                         int T, int Q) {
    extern __shared__ __align__(128) float dbuf[];   // [8 warps][NBUF][EROW]

    const int tid  = threadIdx.x;
    const int wid  = tid >> 5;
    const int lane = tid & 31;

    // Per-thread constants for 32 columns: e = j*128 + lane*4 + {0..3}.
    float4 sv[8], bv[8];
#pragma unroll
    for (int j = 0; j < 8; j++) {
        const int eb = j * 128 + lane * 4;
        float acc[4];
#pragma unroll
        for (int jj = 0; jj < 4; jj++) {
            const float* wr = W + (size_t)(eb + jj) * Q;
            float a = 0.0f;
#pragma unroll 8
            for (int q = 0; q < Q; q++) a += __ldg(wr + q);
            acc[jj] = a;
        }
        sv[j] = make_float4(acc[0], acc[1], acc[2], acc[3]);
        bv[j] = make_float4(__ldg(b + eb), __ldg(b + eb + 1),
                            __ldg(b + eb + 2), __ldg(b + eb + 3));
    }

    float* wbuf = dbuf + wid * (NBUF * EROW);

    const int gw      = blockIdx.x * 8 + wid;   // global warp id
    const int gstride = gridDim.x * 8;

    int n = 0;
    for (int t = gw; t < T; t += gstride, ++n) {
        float* bp = wbuf + (n % NBUF) * EROW;

        // Reuse ring slot only after the bulk store issued NBUF iterations
        // ago finished READING smem; up to NBUF-1 groups stay in flight.
        if (lane == 0 && n >= NBUF)
            asm volatile("cp.async.bulk.wait_group.read 2;" ::: "memory");
        __syncwarp();

        const float c = cosf((float)t);
#pragma unroll
        for (int j = 0; j < 8; j++) {
            float4 v;
            v.x = fmaf(c, sv[j].x, bv[j].x);
            v.y = fmaf(c, sv[j].y, bv[j].y);
            v.z = fmaf(c, sv[j].z, bv[j].z);
            v.w = fmaf(c, sv[j].w, bv[j].w);
            *reinterpret_cast<float4*>(bp + j * 128 + lane * 4) = v;
        }
        __syncwarp();

        if (lane == 0) {
            // Order this warp's generic-proxy STS before the async-proxy read.
            asm volatile("fence.proxy.async.shared::cta;" ::: "memory");
            const unsigned src = (unsigned)__cvta_generic_to_shared(bp);
            asm volatile(
                "cp.async.bulk.global.shared::cta.bulk_group [%0], [%1], %2;"
                :: "l"(out + (size_t)t * EROW), "r"(src), "r"(EROW * 4)
                : "memory");
            asm volatile("cp.async.bulk.commit_group;" ::: "memory");
        }
    }

    // Drain all outstanding bulk stores before exit.
    if (lane == 0)
        asm volatile("cp.async.bulk.wait_group 0;" ::: "memory");
}

// Fallback (direct STG) for the E != 1024 case — never expected here.
__global__ __launch_bounds__(256, 8)
void pequant_fallback_kernel(const float* __restrict__ W,
                             const float* __restrict__ b,
                             float* __restrict__ out,
                             int T, int E, int Q) {
    const int tid = threadIdx.x;
    const int e0  = tid * 4;
    float s[4], bb[4];
#pragma unroll
    for (int j = 0; j < 4; j++) {
        const int e = e0 + j;
        float acc = 0.0f;
        const float* wr = W + (size_t)e * Q;
        for (int q = 0; q < Q; q++) acc += wr[q];
        s[j]  = acc;
        bb[j] = b[e];
    }
    for (int t = blockIdx.x; t < T; t += gridDim.x) {
        const float c = cosf((float)t);
        float4 v;
        v.x = fmaf(c, s[0], bb[0]);
        v.y = fmaf(c, s[1], bb[1]);
        v.z = fmaf(c, s[2], bb[2]);
        v.w = fmaf(c, s[3], bb[3]);
        *reinterpret_cast<float4*>(out + (size_t)t * E + e0) = v;
    }
}

extern "C" void kernel_launch(void* const* d_in, const int* in_sizes, int n_in,
                              void* d_out, int out_size) {
    // metadata order: x (unused), W [E, Q], b [E]
    const float* W = (const float*)d_in[1];
    const float* b = (const float*)d_in[2];
    float* out = (float*)d_out;

    const int E = in_sizes[2];            // 1024
    const int Q = in_sizes[1] / E;        // 8
    const int T = out_size / E;           // 65536

    if (E == EROW) {
        const int smem_bytes = 8 * NBUF * EROW * 4;   // 96 KB dynamic
        static int attr_done = 0;
        // cudaFuncSetAttribute is idempotent host-side configuration (not an
        // allocation, not a stream op); safe under graph capture.
        cudaFuncSetAttribute(pequant_warp_kernel,
                             cudaFuncAttributeMaxDynamicSharedMemorySize,
                             smem_bytes);
        (void)attr_done;
        int blocks = 148 * 2;             // 2 CTAs/SM @ 96 KB smem
        pequant_warp_kernel<<<blocks, 256, smem_bytes>>>(W, b, out, T, Q);
    } else {
        int blocks = 2048;
        if (blocks > T) blocks = T;
        pequant_fallback_kernel<<<blocks, E / 4>>>(W, b, out, T, E, Q);
    }
}